// round 13
// baseline (speedup 1.0000x reference)
#include <cuda_runtime.h>
#include <cuda_fp16.h>
#include <math.h>
#include <stdint.h>

#define MTOK 2048
#define TT   1024
#define DD   512
#define DI_  1024
#define DS_  16
#define LYR  4
#define VOC  32000
#define TC   32
#define NCH  32

// Weights stored pre-scaled by 32 (keeps small weights in fp16 normal range);
// GEMM epilogue multiplies the fp32 accumulator by 1/32.
#define WSCALE 32.0f
#define WSCALE_INV 0.03125f

// ===================== PTX helpers (plain sm_103-safe) =====================
__device__ __forceinline__ uint32_t smem_u32(const void* p) {
    uint32_t a;
    asm("{ .reg .u64 t; cvta.to.shared.u64 t, %1; cvt.u32.u64 %0, t; }"
        : "=r"(a) : "l"(p));
    return a;
}
#define CP16(dst, src) \
    asm volatile("cp.async.cg.shared.global [%0], [%1], 16;" \
                 :: "r"(dst), "l"(src) : "memory")
#define CP_COMMIT() asm volatile("cp.async.commit_group;" ::: "memory")
template <int n>
__device__ __forceinline__ void cp_wait() {
    asm volatile("cp.async.wait_group %0;" :: "n"(n) : "memory");
}

__device__ __forceinline__ void ldsm4(uint32_t* r, uint32_t addr) {
    asm volatile("ldmatrix.sync.aligned.m8n8.x4.shared.b16 {%0,%1,%2,%3}, [%4];"
                 : "=r"(r[0]), "=r"(r[1]), "=r"(r[2]), "=r"(r[3]) : "r"(addr));
}
__device__ __forceinline__ void mma16816(float* d, const uint32_t* a,
                                         const uint32_t* b) {
    asm volatile(
        "mma.sync.aligned.m16n8k16.row.col.f32.f16.f16.f32 "
        "{%0,%1,%2,%3}, {%4,%5,%6,%7}, {%8,%9}, {%0,%1,%2,%3};"
        : "+f"(d[0]), "+f"(d[1]), "+f"(d[2]), "+f"(d[3])
        : "r"(a[0]), "r"(a[1]), "r"(a[2]), "r"(a[3]), "r"(b[0]), "r"(b[1]));
}

// ===================== device-global scratch ==============================
__device__ __align__(256) float g_x   [MTOK * DD];
__device__ __align__(256) float g_xdbl[MTOK * 64];
__device__ __align__(256) float g_dt  [MTOK * DI_];
__device__ __align__(256) float g_xpart[4 * MTOK * 64];   // split-K partials

__device__ __align__(256) float g_sD [2 * NCH * DI_ * DS_];
__device__ __align__(256) float g_sV [2 * NCH * DI_ * DS_];

// fp16 activations
__device__ __align__(256) __half g_xzh [MTOK * 2048];     // W_in out (u | z)
__device__ __align__(256) __half g_hh  [MTOK * DD];
__device__ __align__(256) __half g_uh  [MTOK * DI_];
__device__ __align__(256) __half g_xdh [MTOK * 64];
__device__ __align__(256) __half g_yh  [MTOK * DI_];
__device__ __align__(256) __half g_hidh[MTOK * 2048];
__device__ __align__(256) __half g_xh  [MTOK * DD];

// fp16 weights (pre-scaled by 32)
__device__ __align__(256) __half g_Winh [LYR * 2048 * DD];
__device__ __align__(256) __half g_Wxph [LYR * 64 * DI_];
__device__ __align__(256) __half g_Wdth [LYR * DI_ * 32];
__device__ __align__(256) __half g_Wouth[LYR * DD * DI_];
__device__ __align__(256) __half g_Wf1h [LYR * 2048 * DD];
__device__ __align__(256) __half g_Wf2h [LYR * DD * 2048];
__device__ __align__(256) __half g_lmh  [VOC * DD];

// ===================== small kernels ======================================
__global__ void embed_kernel(const int* __restrict__ idx,
                             const float* __restrict__ tok,
                             const float* __restrict__ pos) {
    int i = blockIdx.x * 256 + threadIdx.x;
    int token = i >> 7;
    int c = i & 127;
    int t = token & (TT - 1);
    int row = idx[token];
    float4 a = ((const float4*)tok)[row * 128 + c];
    float4 p = ((const float4*)pos)[t * 128 + c];
    a.x += p.x; a.y += p.y; a.z += p.z; a.w += p.w;
    ((float4*)g_x)[i] = a;
}

// weight convert with 4 independent float4 accesses per thread (MLP=4)
__global__ void wconv_kernel(const float* __restrict__ in,
                             __half* __restrict__ hi, int n4) {
    int i0 = blockIdx.x * 1024 + threadIdx.x;
    #pragma unroll
    for (int j = 0; j < 4; j++) {
        int i = i0 + j * 256;
        if (i < n4) {
            float4 v = ((const float4*)in)[i];
            ((__half2*)hi)[i * 2 + 0] =
                __half2{__float2half_rn(v.x * WSCALE), __float2half_rn(v.y * WSCALE)};
            ((__half2*)hi)[i * 2 + 1] =
                __half2{__float2half_rn(v.z * WSCALE), __float2half_rn(v.w * WSCALE)};
        }
    }
}

__global__ void ln_kernel(const float* __restrict__ x,
                          const float* __restrict__ g,
                          const float* __restrict__ bta,
                          __half* __restrict__ oh) {
    int token = blockIdx.x;
    int tid = threadIdx.x;
    float4 v = ((const float4*)(x + token * DD))[tid];
    float s = v.x + v.y + v.z + v.w;
    __shared__ float red[8];
    #pragma unroll
    for (int o = 16; o > 0; o >>= 1) s += __shfl_xor_sync(0xffffffffu, s, o);
    if ((tid & 31) == 0) red[tid >> 5] = s;
    __syncthreads();
    float mean = (red[0] + red[1] + red[2] + red[3]) * (1.0f / 512.0f);
    float dx = v.x - mean, dy = v.y - mean, dz = v.z - mean, dw = v.w - mean;
    float q = dx * dx + dy * dy + dz * dz + dw * dw;
    #pragma unroll
    for (int o = 16; o > 0; o >>= 1) q += __shfl_xor_sync(0xffffffffu, q, o);
    if ((tid & 31) == 0) red[4 + (tid >> 5)] = q;
    __syncthreads();
    float var = (red[4] + red[5] + red[6] + red[7]) * (1.0f / 512.0f);
    float r = rsqrtf(var + 1e-5f);
    float4 gg = ((const float4*)g)[tid];
    float4 bb = ((const float4*)bta)[tid];
    float o0 = dx * r * gg.x + bb.x, o1 = dy * r * gg.y + bb.y;
    float o2 = dz * r * gg.z + bb.z, o3 = dw * r * gg.w + bb.w;
    ((__half2*)(oh + token * DD))[tid * 2 + 0] =
        __half2{__float2half_rn(o0), __float2half_rn(o1)};
    ((__half2*)(oh + token * DD))[tid * 2 + 1] =
        __half2{__float2half_rn(o2), __float2half_rn(o3)};
}

// conv: one thread = 4 consecutive tokens x 1 channel
__global__ void conv_silu_kernel(const float* __restrict__ w,
                                 const float* __restrict__ cb) {
    int i = blockIdx.x * 256 + threadIdx.x;   // (token_group, d)
    int tg = i >> 10;
    int d = i & (DI_ - 1);
    int token0 = tg << 2;
    int t0 = token0 & (TT - 1);
    const __half* col = g_xzh + d;
    float4 wv = *(const float4*)(w + d * 4);
    float bias = cb[d];
    float xm3 = 0.f, xm2 = 0.f, xm1 = 0.f;
    if (t0 != 0) {
        xm3 = __half2float(col[(size_t)(token0 - 3) * 2048]);
        xm2 = __half2float(col[(size_t)(token0 - 2) * 2048]);
        xm1 = __half2float(col[(size_t)(token0 - 1) * 2048]);
    }
    float x0 = __half2float(col[(size_t)(token0 + 0) * 2048]);
    float x1 = __half2float(col[(size_t)(token0 + 1) * 2048]);
    float x2 = __half2float(col[(size_t)(token0 + 2) * 2048]);
    float x3 = __half2float(col[(size_t)(token0 + 3) * 2048]);
    float o0 = bias + wv.x * xm3 + wv.y * xm2 + wv.z * xm1 + wv.w * x0;
    float o1 = bias + wv.x * xm2 + wv.y * xm1 + wv.z * x0 + wv.w * x1;
    float o2 = bias + wv.x * xm1 + wv.y * x0 + wv.z * x1 + wv.w * x2;
    float o3 = bias + wv.x * x0 + wv.y * x1 + wv.z * x2 + wv.w * x3;
    float u0 = o0 / (1.0f + __expf(-o0));
    float u1 = o1 / (1.0f + __expf(-o1));
    float u2 = o2 / (1.0f + __expf(-o2));
    float u3 = o3 / (1.0f + __expf(-o3));
    size_t base = (size_t)token0 * DI_ + d;
    g_uh[base + 0 * DI_] = __float2half_rn(u0);
    g_uh[base + 1 * DI_] = __float2half_rn(u1);
    g_uh[base + 2 * DI_] = __float2half_rn(u2);
    g_uh[base + 3 * DI_] = __float2half_rn(u3);
}

// split-K reduce for x_dbl: sum 4 partials -> fp32 + fp16
__global__ void xdbl_reduce_kernel() {
    int i = blockIdx.x * 256 + threadIdx.x;   // float4 index, 32768 total
    const float4* p = (const float4*)g_xpart;
    float4 a = p[i], b = p[i + 32768], c = p[i + 65536], e = p[i + 98304];
    float4 s;
    s.x = (a.x + b.x) + (c.x + e.x);
    s.y = (a.y + b.y) + (c.y + e.y);
    s.z = (a.z + b.z) + (c.z + e.z);
    s.w = (a.w + b.w) + (c.w + e.w);
    ((float4*)g_xdbl)[i] = s;
    ((__half2*)g_xdh)[i * 2 + 0] = __half2{__float2half_rn(s.x), __float2half_rn(s.y)};
    ((__half2*)g_xdh)[i * 2 + 1] = __half2{__float2half_rn(s.z), __float2half_rn(s.w)};
}

// ======== chunked selective scan (2 phases) ===============================
__device__ __forceinline__ void powers16(float r, float* p) {
    float r2 = r * r, r4 = r2 * r2, r8 = r4 * r4;
    p[0] = r;        p[1] = r2;       p[2] = r2 * r;   p[3] = r4;
    p[4] = r4 * r;   p[5] = r4 * r2;  p[6] = r4 * p[2]; p[7] = r8;
    p[8] = r8 * r;   p[9] = r8 * r2;  p[10] = r8 * p[2]; p[11] = r8 * r4;
    p[12] = r8 * p[4]; p[13] = r8 * p[5]; p[14] = r8 * p[6]; p[15] = r8 * r8;
}

__global__ void scan_p1(const float* __restrict__ A_log) {
    __shared__ float sB[TC][16];
    const int d = blockIdx.x * 128 + threadIdx.x;
    const int ch = blockIdx.y, b = blockIdx.z;
    const int t0 = ch * TC;
    for (int i = threadIdx.x; i < TC * 16; i += 128) {
        int tt = i >> 4, s = i & 15;
        sB[tt][s] = g_xdbl[(size_t)(b * TT + t0 + tt) * 64 + 32 + s];
    }
    __syncthreads();
    float es[16]; bool fast = true;
    #pragma unroll
    for (int s = 0; s < 16; s++) {
        es[s] = expf(A_log[d * 16 + s]);
        fast = fast && (fabsf(es[s] - (float)(s + 1)) < 1e-3f);
    }
    float h[16];
    #pragma unroll
    for (int s = 0; s < 16; s++) h[s] = 0.0f;
    float S = 0.0f;
    const float* pdt = g_dt + (size_t)(b * TT + t0) * DI_ + d;
    const __half* pu = g_uh + (size_t)(b * TT + t0) * DI_ + d;

    float cd[4], cu[4];
    #pragma unroll
    for (int j = 0; j < 4; j++) {
        cd[j] = pdt[j * DI_]; cu[j] = __half2float(pu[j * DI_]);
    }
    for (int tg = 0; tg < TC / 4; tg++) {
        float nd[4], nu[4];
        if (tg + 1 < TC / 4) {
            int t1 = (tg + 1) * 4;
            #pragma unroll
            for (int j = 0; j < 4; j++) {
                nd[j] = pdt[(t1 + j) * DI_];
                nu[j] = __half2float(pu[(t1 + j) * DI_]);
            }
        }
        #pragma unroll
        for (int j = 0; j < 4; j++) {
            int t = tg * 4 + j;
            float dt = cd[j];
            S += dt;
            float x = dt * cu[j];
            float p[16];
            if (fast) powers16(__expf(-dt), p);
            else {
                #pragma unroll
                for (int s = 0; s < 16; s++) p[s] = __expf(-dt * es[s]);
            }
            #pragma unroll
            for (int s = 0; s < 16; s++) h[s] = p[s] * h[s] + x * sB[t][s];
        }
        if (tg + 1 < TC / 4) {
            #pragma unroll
            for (int j = 0; j < 4; j++) { cd[j] = nd[j]; cu[j] = nu[j]; }
        }
    }
    size_t o = (((size_t)b * NCH + ch) * DI_ + d) * 16;
    #pragma unroll
    for (int s = 0; s < 16; s++) {
        g_sV[o + s] = h[s];
        g_sD[o + s] = __expf(-S * es[s]);
    }
}

__global__ void scan_p3(const float* __restrict__ A_log,
                        const float* __restrict__ D_p) {
    __shared__ float sB[TC][16], sC[TC][16];
    const int d = blockIdx.x * 128 + threadIdx.x;
    const int ch = blockIdx.y, b = blockIdx.z;
    const int t0 = ch * TC;
    for (int i = threadIdx.x; i < TC * 16; i += 128) {
        int tt = i >> 4, s = i & 15;
        size_t base = (size_t)(b * TT + t0 + tt) * 64;
        sB[tt][s] = g_xdbl[base + 32 + s];
        sC[tt][s] = g_xdbl[base + 48 + s];
    }
    __syncthreads();
    float es[16]; bool fast = true;
    #pragma unroll
    for (int s = 0; s < 16; s++) {
        es[s] = expf(A_log[d * 16 + s]);
        fast = fast && (fabsf(es[s] - (float)(s + 1)) < 1e-3f);
    }
    float h[16];
    #pragma unroll
    for (int s = 0; s < 16; s++) h[s] = 0.0f;
    for (int c = 0; c < ch; c++) {
        size_t o = (((size_t)b * NCH + c) * DI_ + d) * 16;
        #pragma unroll
        for (int s = 0; s < 16; s++) h[s] = g_sD[o + s] * h[s] + g_sV[o + s];
    }
    const float Dp = D_p[d];
    const float* pdt = g_dt + (size_t)(b * TT + t0) * DI_ + d;
    const __half* pu = g_uh + (size_t)(b * TT + t0) * DI_ + d;
    const __half* pz = g_xzh + (size_t)(b * TT + t0) * 2048 + DI_ + d;
    __half* pyh = g_yh + (size_t)(b * TT + t0) * DI_ + d;

    float cd[4], cu[4], cz[4];
    #pragma unroll
    for (int j = 0; j < 4; j++) {
        cd[j] = pdt[j * DI_];
        cu[j] = __half2float(pu[j * DI_]);
        cz[j] = __half2float(pz[j * 2048]);
    }
    for (int tg = 0; tg < TC / 4; tg++) {
        float nd[4], nu[4], nz[4];
        if (tg + 1 < TC / 4) {
            int t1 = (tg + 1) * 4;
            #pragma unroll
            for (int j = 0; j < 4; j++) {
                nd[j] = pdt[(t1 + j) * DI_];
                nu[j] = __half2float(pu[(t1 + j) * DI_]);
                nz[j] = __half2float(pz[(t1 + j) * 2048]);
            }
        }
        #pragma unroll
        for (int j = 0; j < 4; j++) {
            int t = tg * 4 + j;
            float dt = cd[j], u = cu[j], z = cz[j];
            float x = dt * u;
            float p[16];
            if (fast) powers16(__expf(-dt), p);
            else {
                #pragma unroll
                for (int s = 0; s < 16; s++) p[s] = __expf(-dt * es[s]);
            }
            #pragma unroll
            for (int s = 0; s < 16; s++) h[s] = p[s] * h[s] + x * sB[t][s];
            float q[8];
            #pragma unroll
            for (int i = 0; i < 8; i++)
                q[i] = fmaf(h[2 * i], sC[t][2 * i], h[2 * i + 1] * sC[t][2 * i + 1]);
            float yp = ((q[0] + q[1]) + (q[2] + q[3])) + ((q[4] + q[5]) + (q[6] + q[7]));
            float yv = yp + u * Dp;
            float ov = yv * (z / (1.0f + __expf(-z)));
            pyh[t * DI_] = __float2half_rn(ov);
        }
        if (tg + 1 < TC / 4) {
            #pragma unroll
            for (int j = 0; j < 4; j++) { cd[j] = nd[j]; cu[j] = nu[j]; cz[j] = nz[j]; }
        }
    }
}

// ===================== HMMA fp16 GEMM (multi-stage, optional split-K) =====
#define F_BIAS 1
#define F_RELU 2
#define F_SOFT 4
#define F_RES  8
#define F_WF32 16
#define F_WHALF 32

template <int BM, int BN, int WGM, int WGN, int NWARP, int STAGES, int FLAGS>
__global__ __launch_bounds__(NWARP * 32) void tgemm(
    int M, int N, int K, int lda, int ldb,
    const __half* __restrict__ A, const __half* __restrict__ Bw,
    const float* __restrict__ bias, const float* __restrict__ res,
    float* __restrict__ Cf, __half* __restrict__ Ch) {
    extern __shared__ char smem[];
    constexpr int NT = NWARP * 32;
    constexpr int PITCH = 80;
    constexpr int ASZ = BM * PITCH;
    constexpr int BSZ = BN * PITCH;
    constexpr int STAGE = ASZ + BSZ;
    constexpr int WROWS = BM / WGM, WCOLS = BN / WGN;
    constexpr int MI = WROWS / 16, NI = WCOLS / 8, NP = NI / 2;
    const int tid = threadIdx.x, lane = tid & 31, wid = tid >> 5;
    const int wm = wid / WGN, wn = wid % WGN;
    const int bm = blockIdx.y * BM, bn = blockIdx.x * BN;
    const int kbase = blockIdx.z * K;
    const uint32_t sb = smem_u32(smem);
    const int nc = K / 32;
    if (FLAGS & F_WF32) Cf += (size_t)blockIdx.z * M * N;

    float acc[MI][NI][4];
    #pragma unroll
    for (int i = 0; i < MI; i++)
        #pragma unroll
        for (int j = 0; j < NI; j++)
            #pragma unroll
            for (int q = 0; q < 4; q++) acc[i][j][q] = 0.0f;

    auto prefetch = [&](int c, int slot) {
        if (c >= nc) return;
        const uint32_t sbase = sb + slot * STAGE;
        const int k0 = kbase + c * 32;
        #pragma unroll
        for (int i = 0; i < (BM * 4 + NT - 1) / NT; i++) {
            int ch = tid + i * NT;
            if ((BM * 4 % NT == 0) || ch < BM * 4) {
                int row = ch >> 2, kc = ch & 3;
                uint32_t doff = row * PITCH + kc * 16;
                size_t goff = (size_t)(bm + row) * lda + k0 + kc * 8;
                CP16(sbase + doff, (const char*)(A + goff));
            }
        }
        #pragma unroll
        for (int i = 0; i < (BN * 4 + NT - 1) / NT; i++) {
            int ch = tid + i * NT;
            if ((BN * 4 % NT == 0) || ch < BN * 4) {
                int row = ch >> 2, kc = ch & 3;
                uint32_t doff = row * PITCH + kc * 16;
                size_t goff = (size_t)(bn + row) * ldb + k0 + kc * 8;
                CP16(sbase + ASZ + doff, (const char*)(Bw + goff));
            }
        }
    };

    auto compute = [&](int s) {
        const uint32_t sbase = sb + s * STAGE;
        const uint32_t arow = (uint32_t)(lane & 15);
        const uint32_t asel = (uint32_t)((lane >> 4) * 16);
        #pragma unroll
        for (int kk = 0; kk < 2; kk++) {
            const uint32_t kb = kk * 32;
            uint32_t a[MI][4];
            #pragma unroll
            for (int mi = 0; mi < MI; mi++) {
                uint32_t ad = sbase + (wm * WROWS + mi * 16 + arow) * PITCH + kb + asel;
                ldsm4(a[mi], ad);
            }
            #pragma unroll
            for (int p = 0; p < NP; p++) {
                uint32_t bd = sbase + ASZ +
                              (wn * WCOLS + p * 16 + arow) * PITCH + kb + asel;
                uint32_t t4[4];
                ldsm4(t4, bd);
                uint32_t b0[2] = {t4[0], t4[2]}, b1[2] = {t4[1], t4[3]};
                #pragma unroll
                for (int mi = 0; mi < MI; mi++) {
                    mma16816(acc[mi][2 * p], a[mi], b0);
                    mma16816(acc[mi][2 * p + 1], a[mi], b1);
                }
            }
        }
    };

    #pragma unroll
    for (int c = 0; c < STAGES - 1; c++) { prefetch(c, c); CP_COMMIT(); }
    int ps = (STAGES - 1) % STAGES, cs = 0;
    for (int c = 0; c < nc; c++) {
        cp_wait<STAGES - 2>();
        __syncthreads();
        prefetch(c + STAGES - 1, ps); CP_COMMIT();
        compute(cs);
        ps = (ps + 1 == STAGES) ? 0 : ps + 1;
        cs = (cs + 1 == STAGES) ? 0 : cs + 1;
    }

    // ---- epilogue ----
    #pragma unroll
    for (int mi = 0; mi < MI; mi++) {
        #pragma unroll
        for (int ni = 0; ni < NI; ni++) {
            const int r0 = bm + wm * WROWS + mi * 16 + (lane >> 2);
            const int c0 = bn + wn * WCOLS + ni * 8 + (lane & 3) * 2;
            #pragma unroll
            for (int hh = 0; hh < 2; hh++) {
                const int r = r0 + hh * 8;
                float v0 = acc[mi][ni][hh * 2 + 0] * WSCALE_INV;
                float v1 = acc[mi][ni][hh * 2 + 1] * WSCALE_INV;
                if (FLAGS & F_BIAS) { v0 += bias[c0]; v1 += bias[c0 + 1]; }
                if (FLAGS & F_RELU) { v0 = fmaxf(v0, 0.f); v1 = fmaxf(v1, 0.f); }
                if (FLAGS & F_SOFT) {
                    v0 = (v0 > 20.f) ? v0 : log1pf(expf(v0));
                    v1 = (v1 > 20.f) ? v1 : log1pf(expf(v1));
                }
                if (FLAGS & F_RES) {
                    float2 rr = *(const float2*)(res + (size_t)r * N + c0);
                    v0 += rr.x; v1 += rr.y;
                }
                if (FLAGS & F_WF32) {
                    *(float2*)(Cf + (size_t)r * N + c0) = make_float2(v0, v1);
                }
                if (FLAGS & F_WHALF) {
                    *(__half2*)(Ch + (size_t)r * N + c0) =
                        __half2{__float2half_rn(v0), __float2half_rn(v1)};
                }
            }
        }
    }
}

// ===================== host orchestration =================================
template <int BM, int BN, int WGM, int WGN, int NWARP, int STAGES, int FLAGS>
static void launch_tgemm(int M, int N, int K, int lda, int ldb,
                         const __half* A, const __half* Bw,
                         const float* bias, const float* res,
                         float* Cf, __half* Ch, int KS = 1) {
    constexpr int PITCH = 80;
    constexpr int STAGE = BM * PITCH + BN * PITCH;
    const int smem_bytes = STAGES * STAGE;
    cudaFuncSetAttribute(tgemm<BM, BN, WGM, WGN, NWARP, STAGES, FLAGS>,
                         cudaFuncAttributeMaxDynamicSharedMemorySize, smem_bytes);
    dim3 grid(N / BN, M / BM, KS);
    tgemm<BM, BN, WGM, WGN, NWARP, STAGES, FLAGS>
        <<<grid, NWARP * 32, smem_bytes>>>(M, N, K / KS, lda, ldb,
        A, Bw, bias, res, Cf, Ch);
}

extern "C" void kernel_launch(void* const* d_in, const int* in_sizes, int n_in,
                              void* d_out, int out_size) {
    const int*   idx   = (const int*)d_in[0];
    const float* tok   = (const float*)d_in[1];
    const float* pos   = (const float*)d_in[2];
    const float* ln1g  = (const float*)d_in[3];
    const float* ln1b  = (const float*)d_in[4];
    const float* W_in  = (const float*)d_in[5];
    const float* convw = (const float*)d_in[6];
    const float* convb = (const float*)d_in[7];
    const float* W_xp  = (const float*)d_in[8];
    const float* W_dt  = (const float*)d_in[9];
    const float* b_dt  = (const float*)d_in[10];
    const float* A_log = (const float*)d_in[11];
    const float* D_p   = (const float*)d_in[12];
    const float* W_out = (const float*)d_in[13];
    const float* ln2g  = (const float*)d_in[14];
    const float* ln2b  = (const float*)d_in[15];
    const float* W_f1  = (const float*)d_in[16];
    const float* b_f1  = (const float*)d_in[17];
    const float* W_f2  = (const float*)d_in[18];
    const float* b_f2  = (const float*)d_in[19];
    const float* lm_w  = (const float*)d_in[20];
    const float* lm_b  = (const float*)d_in[21];
    float* out = (float*)d_out;

    float *px, *pxd, *pdt, *pxpart;
    __half *pxzh, *phh, *puh, *pxdh, *pyh, *phidh, *pxh;
    __half *wIn, *wXp, *wDt, *wOut, *wF1, *wF2, *wLm;

    cudaGetSymbolAddress((void**)&px,   g_x);
    cudaGetSymbolAddress((void**)&pxd,  g_xdbl);
    cudaGetSymbolAddress((void**)&pdt,  g_dt);
    cudaGetSymbolAddress((void**)&pxpart, g_xpart);
    cudaGetSymbolAddress((void**)&pxzh, g_xzh);
    cudaGetSymbolAddress((void**)&phh,  g_hh);
    cudaGetSymbolAddress((void**)&puh,  g_uh);
    cudaGetSymbolAddress((void**)&pxdh, g_xdh);
    cudaGetSymbolAddress((void**)&pyh,  g_yh);
    cudaGetSymbolAddress((void**)&phidh,g_hidh);
    cudaGetSymbolAddress((void**)&pxh,  g_xh);
    cudaGetSymbolAddress((void**)&wIn,  g_Winh);
    cudaGetSymbolAddress((void**)&wXp,  g_Wxph);
    cudaGetSymbolAddress((void**)&wDt,  g_Wdth);
    cudaGetSymbolAddress((void**)&wOut, g_Wouth);
    cudaGetSymbolAddress((void**)&wF1,  g_Wf1h);
    cudaGetSymbolAddress((void**)&wF2,  g_Wf2h);
    cudaGetSymbolAddress((void**)&wLm,  g_lmh);

    auto wconv = [&](const float* src, __half* h, long n) {
        int n4 = (int)(n / 4);
        wconv_kernel<<<(n4 + 1023) / 1024, 256>>>(src, h, n4);
    };

    wconv(W_in,  wIn,  (long)LYR * 2048 * DD);
    wconv(W_xp,  wXp,  (long)LYR * 64 * DI_);
    wconv(W_dt,  wDt,  (long)LYR * DI_ * 32);
    wconv(W_out, wOut, (long)LYR * DD * DI_);
    wconv(W_f1,  wF1,  (long)LYR * 2048 * DD);
    wconv(W_f2,  wF2,  (long)LYR * DD * 2048);
    wconv(lm_w,  wLm,  (long)VOC * DD);

    embed_kernel<<<1024, 256>>>(idx, tok, pos);

    for (int l = 0; l < LYR; l++) {
        ln_kernel<<<MTOK, 128>>>(px, ln1g + l * DD, ln1b + l * DD, phh);
        // xz = h @ W_in^T  [2048,2048] -> fp16
        launch_tgemm<128, 256, 4, 4, 16, 4, F_WHALF>(MTOK, 2048, DD, DD, DD,
            phh, wIn + (long)l * 2048 * DD, nullptr, nullptr, nullptr, pxzh);
        conv_silu_kernel<<<2048, 256>>>(convw + l * DI_ * 4, convb + l * DI_);
        // x_dbl = u @ W_xp^T  [2048,64]  — split-K=4 + reduce
        launch_tgemm<64, 64, 4, 4, 16, 4, F_WF32>(MTOK, 64, DI_, DI_, DI_,
            puh, wXp + (long)l * 64 * DI_, nullptr, nullptr, pxpart, nullptr, 4);
        xdbl_reduce_kernel<<<128, 256>>>();
        launch_tgemm<128, 128, 4, 4, 16, 4, F_BIAS | F_SOFT | F_WF32>(
            MTOK, DI_, 32, 64, 32,
            pxdh, wDt + (long)l * DI_ * 32, b_dt + l * DI_, nullptr, pdt, nullptr);
        scan_p1<<<dim3(8, NCH, 2), 128>>>(A_log + (long)l * DI_ * DS_);
        scan_p3<<<dim3(8, NCH, 2), 128>>>(A_log + (long)l * DI_ * DS_, D_p + l * DI_);
        launch_tgemm<64, 128, 2, 8, 16, 4, F_RES | F_WF32>(MTOK, DD, DI_, DI_, DI_,
            pyh, wOut + (long)l * DD * DI_, nullptr, px, px, nullptr);
        ln_kernel<<<MTOK, 128>>>(px, ln2g + l * DD, ln2b + l * DD, phh);
        // hidden = relu(h @ W_f1^T + b_f1)  [2048,2048]
        launch_tgemm<128, 256, 4, 4, 16, 4, F_BIAS | F_RELU | F_WHALF>(
            MTOK, 2048, DD, DD, DD,
            phh, wF1 + (long)l * 2048 * DD, b_f1 + l * 2048, nullptr, nullptr, phidh);
        launch_tgemm<64, 128, 2, 8, 16, 4, F_BIAS | F_RES | F_WF32 | F_WHALF>(
            MTOK, DD, 2048, 2048, 2048,
            phidh, wF2 + (long)l * DD * 2048, b_f2 + l * DD, px, px, pxh);
    }

    // logits = x @ lm_w^T + lm_b  [2048,32000]
    launch_tgemm<128, 256, 4, 4, 16, 4, F_BIAS | F_WF32>(MTOK, VOC, DD, DD, DD,
        pxh, wLm, lm_b, nullptr, out, nullptr);
}